// round 1
// baseline (speedup 1.0000x reference)
#include <cuda_runtime.h>
#include <math.h>

// Problem constants (fixed by the dataset)
#define Bn 4
#define Nn 4096
#define En 16384
// D=256, A=64, T=16, HALF=8, STEPS=3

// ---------------------------------------------------------------------------
// Static device scratch (allocation-free rule: __device__ globals)
// ---------------------------------------------------------------------------
__device__ __align__(16) float g_S[(size_t)8 * Nn * 2048];     // [b*2+dir][n][t*256+j]  256 MB
__device__ __align__(16) float g_cnt[(size_t)8 * Nn * 8];      // [b*2+dir][n][t]          1 MB
__device__ __align__(16) float g_AG[(size_t)Bn * Nn * 768];    // [a_in | a_out | h or r*h]
__device__ __align__(16) float g_RZ[(size_t)Bn * Nn * 512];    // [r | z]
__device__ __align__(16) float g_HH[(size_t)Bn * Nn * 256];    // h_hat
__device__ __align__(16) float g_h[(size_t)Bn * Nn * 256];     // node state
__device__ __align__(16) float g_ann[(size_t)Bn * Nn * 64];    // annotation
__device__ __align__(16) float g_WT[16 * 256 * 256];           // WT[t][j][i] = W[t][i][j]
__device__ __align__(16) float g_WrzT[768 * 512];              // [k][i] : i<256 -> Wr[i][k], else Wz
__device__ __align__(16) float g_WhT[768 * 256];               // [k][i] = Wh[i][k]
__device__ __align__(16) float g_brz[512];
__device__ float g_nodeval[Bn * Nn];

// ---------------------------------------------------------------------------
// Generic fp32 GEMM: C[m, n0+j] = act( sum_k A[m,k]*B[k,n] + bias[n] )
// 128x128 tile, BK=16, 256 threads, 8x8 per thread.
// grid.x = M/128, grid.y = Nout/128. A row-major lda, B row-major ldb.
// ---------------------------------------------------------------------------
template <int ACT>
__device__ __forceinline__ void gemm128(const float* __restrict__ A, int lda,
                                        const float* __restrict__ B, int ldb,
                                        float* __restrict__ C, int ldc,
                                        const float* __restrict__ bias, int K)
{
    __shared__ float As[16][132];
    __shared__ float Bs[16][128];
    const int t = threadIdx.x;
    const int m0 = blockIdx.x * 128;
    const int n0 = blockIdx.y * 128;
    const int arow = t >> 2;          // 0..63
    const int acol = (t & 3) << 2;    // 0,4,8,12
    const int brow = t >> 5;          // 0..7
    const int bcol = (t & 31) << 2;   // 0..124
    const float* Ap  = A + (size_t)(m0 + arow) * lda + acol;
    const float* Ap2 = Ap + (size_t)64 * lda;
    const float* Bp  = B + (size_t)brow * ldb + n0 + bcol;
    const float* Bp2 = Bp + (size_t)8 * ldb;
    const int tx = t & 15, ty = t >> 4;

    float acc[8][8];
#pragma unroll
    for (int i = 0; i < 8; i++)
#pragma unroll
        for (int j = 0; j < 8; j++) acc[i][j] = 0.f;

    for (int k0 = 0; k0 < K; k0 += 16) {
        float4 a0 = *(const float4*)Ap;
        float4 a1 = *(const float4*)Ap2;
        float4 b0 = *(const float4*)Bp;
        float4 b1 = *(const float4*)Bp2;
        __syncthreads();
        As[acol + 0][arow] = a0.x; As[acol + 1][arow] = a0.y;
        As[acol + 2][arow] = a0.z; As[acol + 3][arow] = a0.w;
        As[acol + 0][64 + arow] = a1.x; As[acol + 1][64 + arow] = a1.y;
        As[acol + 2][64 + arow] = a1.z; As[acol + 3][64 + arow] = a1.w;
        *(float4*)&Bs[brow][bcol]     = b0;
        *(float4*)&Bs[brow + 8][bcol] = b1;
        __syncthreads();
        Ap += 16; Ap2 += 16;
        Bp += (size_t)16 * ldb; Bp2 += (size_t)16 * ldb;
#pragma unroll
        for (int kk = 0; kk < 16; kk++) {
            float ar[8], brg[8];
            *(float4*)&ar[0]  = *(const float4*)&As[kk][ty * 8];
            *(float4*)&ar[4]  = *(const float4*)&As[kk][ty * 8 + 4];
            *(float4*)&brg[0] = *(const float4*)&Bs[kk][tx * 8];
            *(float4*)&brg[4] = *(const float4*)&Bs[kk][tx * 8 + 4];
#pragma unroll
            for (int i = 0; i < 8; i++)
#pragma unroll
                for (int j = 0; j < 8; j++)
                    acc[i][j] = fmaf(ar[i], brg[j], acc[i][j]);
        }
    }
#pragma unroll
    for (int i = 0; i < 8; i++) {
        float* crow = C + (size_t)(m0 + ty * 8 + i) * ldc + n0 + tx * 8;
        float v[8];
#pragma unroll
        for (int j = 0; j < 8; j++) {
            float x = acc[i][j];
            if (bias) x += bias[n0 + tx * 8 + j];
            if (ACT == 1) x = 1.f / (1.f + expf(-x));
            if (ACT == 2) x = tanhf(x);
            v[j] = x;
        }
        *(float4*)crow       = make_float4(v[0], v[1], v[2], v[3]);
        *(float4*)(crow + 4) = make_float4(v[4], v[5], v[6], v[7]);
    }
}

// ---------------------------------------------------------------------------
// Setup kernels (run every call; inputs may change between calls)
// ---------------------------------------------------------------------------
__global__ void prep_WT(const float* __restrict__ ee) {
    // grid 4096 (t*256+j), block 256 (i) : WT[t][j][i] = W[t][i][j]
    int tj = blockIdx.x;
    int t = tj >> 8, j = tj & 255, i = threadIdx.x;
    g_WT[(size_t)tj * 256 + i] = ee[(size_t)t * 65536 + (size_t)i * 256 + j];
}

__global__ void prep_WrzT(const float* __restrict__ Wr, const float* __restrict__ Wz,
                          const float* __restrict__ br, const float* __restrict__ bz) {
    // grid 768 (k), block 512 (i)
    int k = blockIdx.x, i = threadIdx.x;
    float v = (i < 256) ? Wr[(size_t)i * 768 + k] : Wz[(size_t)(i - 256) * 768 + k];
    g_WrzT[(size_t)k * 512 + i] = v;
    if (k == 0) g_brz[i] = (i < 256) ? br[i] : bz[i - 256];
}

__global__ void prep_WhT(const float* __restrict__ Wh) {
    int k = blockIdx.x, i = threadIdx.x;
    g_WhT[(size_t)k * 256 + i] = Wh[(size_t)i * 768 + k];
}

__global__ void init_h(const int* __restrict__ ann_id, const float* __restrict__ te) {
    // grid 16384 (b*N+n), block 256
    int n = blockIdx.x;
    int i = threadIdx.x;
    int id = ann_id[n];
    float a = 0.f;
    if (i < 64 && id > 0) a = te[(size_t)(id - 1) * 64 + i];
    if (i < 64) g_ann[(size_t)n * 64 + i] = a;
    g_h[(size_t)n * 256 + i] = (i < 64) ? a : 0.f;
}

// ---------------------------------------------------------------------------
// Per-step kernels
// ---------------------------------------------------------------------------
__global__ void zero_S() {
    // grid 65536, block 256, float4 -> exactly 8*4096*2048 floats
    size_t idx = (size_t)blockIdx.x * 256 + threadIdx.x;
    ((float4*)g_S)[idx] = make_float4(0.f, 0.f, 0.f, 0.f);
}

__global__ void zero_cnt() {
    // 8*4096*8 = 262144 floats = 65536 float4 -> grid 256, block 256
    size_t idx = (size_t)blockIdx.x * 256 + threadIdx.x;
    ((float4*)g_cnt)[idx] = make_float4(0.f, 0.f, 0.f, 0.f);
}

__global__ void scatter_k(const int* __restrict__ src, const int* __restrict__ dst,
                          const int* __restrict__ et) {
    // grid B*E = 65536 blocks, block 256 (one channel per thread)
    int eg = blockIdx.x;
    int b = eg >> 14;           // E = 16384
    int i = threadIdx.x;
    int s = __ldg(&src[eg]);
    int d = __ldg(&dst[eg]);
    int t = __ldg(&et[eg]);
    const float* hb = g_h + (size_t)b * Nn * 256;
    float vout = hb[(size_t)d * 256 + i];   // S_out[src] += h[dst]
    float vin  = hb[(size_t)s * 256 + i];   // S_in [dst] += h[src]
    atomicAdd(&g_S[((size_t)(b * 2 + 0) * Nn + s) * 2048 + t * 256 + i], vout);
    atomicAdd(&g_S[((size_t)(b * 2 + 1) * Nn + d) * 2048 + t * 256 + i], vin);
    if (i == 0) atomicAdd(&g_cnt[((size_t)(b * 2 + 0) * Nn + s) * 8 + t], 1.f);
    if (i == 1) atomicAdd(&g_cnt[((size_t)(b * 2 + 1) * Nn + d) * 8 + t], 1.f);
}

__global__ void gemm_agg() {
    // grid (32, 2, 8): z = b*2 + dir ; dir 0 = out (types 0..7, AG cols 256..511)
    //                                dir 1 = in  (types 8..15, AG cols 0..255)
    int z = blockIdx.z;
    int b = z >> 1, dir = z & 1;
    const float* A = g_S + (size_t)z * Nn * 2048;
    const float* B = g_WT + (dir ? (size_t)8 * 256 * 256 : 0);
    float* C = g_AG + (size_t)b * Nn * 768 + (dir ? 0 : 256);
    gemm128<0>(A, 2048, B, 256, C, 768, nullptr, 2048);
}

__global__ void addbias_copyh(const float* __restrict__ eb) {
    // grid 16384 (b*N+n), block 256
    int n = blockIdx.x;
    int b = n >> 12, node = n & 4095;
    int i = threadIdx.x;
    float* ag = g_AG + (size_t)n * 768;
    float ain = ag[i], aout = ag[256 + i];
    const float* cout = g_cnt + ((size_t)(b * 2 + 0) * Nn + node) * 8;
    const float* cin  = g_cnt + ((size_t)(b * 2 + 1) * Nn + node) * 8;
#pragma unroll
    for (int t = 0; t < 8; t++) {
        aout += cout[t] * eb[t * 256 + i];
        ain  += cin[t]  * eb[(t + 8) * 256 + i];
    }
    ag[i] = ain;
    ag[256 + i] = aout;
    ag[512 + i] = g_h[(size_t)n * 256 + i];
}

__global__ void gemm_rz() {
    // grid (128, 4): RZ = sigmoid(AG @ [Wr;Wz]^T + [br;bz])
    gemm128<1>(g_AG, 768, g_WrzT, 512, g_RZ, 512, g_brz, 768);
}

__global__ void set_rh() {
    int n = blockIdx.x;
    int i = threadIdx.x;
    float r = g_RZ[(size_t)n * 512 + i];
    g_AG[(size_t)n * 768 + 512 + i] = r * g_h[(size_t)n * 256 + i];
}

__global__ void gemm_hh(const float* __restrict__ bh) {
    // grid (128, 2): HH = tanh(AG' @ Wh^T + bh)
    gemm128<2>(g_AG, 768, g_WhT, 256, g_HH, 256, bh, 768);
}

__global__ void update_h() {
    int n = blockIdx.x;
    int i = threadIdx.x;
    float z = g_RZ[(size_t)n * 512 + 256 + i];
    float h = g_h[(size_t)n * 256 + i];
    float hh = g_HH[(size_t)n * 256 + i];
    g_h[(size_t)n * 256 + i] = (1.f - z) * h + z * hh;
}

// ---------------------------------------------------------------------------
// Readout
// ---------------------------------------------------------------------------
__global__ void readout_k(const float* __restrict__ Wa, const float* __restrict__ ba,
                          const float* __restrict__ Wo, const float* __restrict__ bo) {
    // one warp per node; grid 2048 blocks x 256 threads
    int warp = (blockIdx.x * blockDim.x + threadIdx.x) >> 5;
    int lane = threadIdx.x & 31;
    const float* hrow = g_h + (size_t)warp * 256;
    const float* arow = g_ann + (size_t)warp * 64;
    float sa = 0.f, so = 0.f;
#pragma unroll
    for (int k = lane; k < 320; k += 32) {
        float v = (k < 256) ? hrow[k] : arow[k - 256];
        sa += v * Wa[k];
        so += v * Wo[k];
    }
#pragma unroll
    for (int off = 16; off; off >>= 1) {
        sa += __shfl_xor_sync(0xffffffffu, sa, off);
        so += __shfl_xor_sync(0xffffffffu, so, off);
    }
    if (lane == 0) {
        float atten = 1.f / (1.f + expf(-(sa + ba[0])));
        float ou = tanhf(so + bo[0]);
        g_nodeval[warp] = atten * ou;
    }
}

__global__ void finalize_k(float* __restrict__ out) {
    __shared__ float sh[256];
    int b = blockIdx.x;
    float s = 0.f;
    for (int i = threadIdx.x; i < Nn; i += 256) s += g_nodeval[(size_t)b * Nn + i];
    sh[threadIdx.x] = s;
    __syncthreads();
    for (int k = 128; k; k >>= 1) {
        if (threadIdx.x < k) sh[threadIdx.x] += sh[threadIdx.x + k];
        __syncthreads();
    }
    if (threadIdx.x == 0) out[b] = 1.f / (1.f + expf(-sh[0]));
}

// ---------------------------------------------------------------------------
// Launch
// ---------------------------------------------------------------------------
extern "C" void kernel_launch(void* const* d_in, const int* in_sizes, int n_in,
                              void* d_out, int out_size) {
    (void)in_sizes; (void)n_in; (void)out_size;
    const int* ann_id = (const int*)d_in[0];
    const int* src    = (const int*)d_in[1];
    const int* dst    = (const int*)d_in[2];
    const int* et     = (const int*)d_in[3];
    const float* ee   = (const float*)d_in[4];
    const float* eb   = (const float*)d_in[5];
    const float* te   = (const float*)d_in[6];
    const float* Wr   = (const float*)d_in[7];
    const float* br   = (const float*)d_in[8];
    const float* Wz   = (const float*)d_in[9];
    const float* bz   = (const float*)d_in[10];
    const float* Wh   = (const float*)d_in[11];
    const float* bh   = (const float*)d_in[12];
    const float* Wa   = (const float*)d_in[13];
    const float* ba   = (const float*)d_in[14];
    const float* Wo   = (const float*)d_in[15];
    const float* bo   = (const float*)d_in[16];
    float* out = (float*)d_out;

    prep_WT<<<4096, 256>>>(ee);
    prep_WrzT<<<768, 512>>>(Wr, Wz, br, bz);
    prep_WhT<<<768, 256>>>(Wh);
    init_h<<<Bn * Nn, 256>>>(ann_id, te);

    for (int step = 0; step < 3; step++) {
        zero_S<<<65536, 256>>>();
        zero_cnt<<<256, 256>>>();
        scatter_k<<<Bn * En, 256>>>(src, dst, et);
        gemm_agg<<<dim3(32, 2, 8), 256>>>();
        addbias_copyh<<<Bn * Nn, 256>>>(eb);
        gemm_rz<<<dim3(128, 4, 1), 256>>>();
        set_rh<<<Bn * Nn, 256>>>();
        gemm_hh<<<dim3(128, 2, 1), 256>>>(bh);
        update_h<<<Bn * Nn, 256>>>();
    }

    readout_k<<<2048, 256>>>(Wa, ba, Wo, bo);
    finalize_k<<<4, 256>>>(out);
}

// round 2
// speedup vs baseline: 2.8885x; 2.8885x over previous
#include <cuda_runtime.h>
#include <math.h>

// Problem constants (fixed by the dataset)
#define Bn 4
#define Nn 4096
#define En 16384
// D=256, A=64, T=16, HALF=8, STEPS=3

// ---------------------------------------------------------------------------
// Static device scratch
// ---------------------------------------------------------------------------
__device__ __align__(16) float g_P[(size_t)64 * Nn * 256];     // [b*16+t][n][i] 256 MB
__device__ __align__(16) float g_AG[(size_t)Bn * Nn * 768];    // [a_in | a_out | h or r*h]
__device__ __align__(16) float g_RZ[(size_t)Bn * Nn * 512];    // [r | z]
__device__ __align__(16) float g_HH[(size_t)Bn * Nn * 256];    // h_hat
__device__ __align__(16) float g_h[(size_t)Bn * Nn * 256];     // node state
__device__ __align__(16) float g_ann[(size_t)Bn * Nn * 64];    // annotation
__device__ __align__(16) float g_Wrz[512 * 768];               // rows: [Wr ; Wz]  (n x k)
__device__ __align__(16) float g_brz[512];
__device__ float g_nodeval[Bn * Nn];

// ---------------------------------------------------------------------------
// TF32 helpers
// ---------------------------------------------------------------------------
__device__ __forceinline__ unsigned f2tf(float x) {
    unsigned r;
    asm("cvt.rna.tf32.f32 %0, %1;" : "=r"(r) : "f"(x));
    return r;
}

__device__ __forceinline__ void mma1688(float* c, const unsigned* a, const unsigned* b) {
    asm volatile(
        "mma.sync.aligned.m16n8k8.row.col.f32.tf32.tf32.f32 "
        "{%0,%1,%2,%3}, {%4,%5,%6,%7}, {%8,%9}, {%0,%1,%2,%3};"
        : "+f"(c[0]), "+f"(c[1]), "+f"(c[2]), "+f"(c[3])
        : "r"(a[0]), "r"(a[1]), "r"(a[2]), "r"(a[3]), "r"(b[0]), "r"(b[1]));
}

// ---------------------------------------------------------------------------
// TF32 GEMM: C[m,n] = act( sum_k A[m,k] * B[n,k] + bias[n] )
//   A: M x K row-major (lda), B: N x K row-major (ldb)  [i.e. mma row.col]
//   Block tile 128x128, BK=32, 256 threads = 8 warps (2 m x 4 n), warp 64x32.
//   M, N multiples of 128; K multiple of 32. grid.x = M/128, grid.y = N/128.
// ACT: 0 none, 1 sigmoid, 2 tanh
// ---------------------------------------------------------------------------
template <int ACT>
__device__ __forceinline__ void gemm_tf32(const float* __restrict__ A, int lda,
                                          const float* __restrict__ B, int ldb,
                                          float* __restrict__ C, int ldc,
                                          const float* __restrict__ bias, int K)
{
    __shared__ unsigned As[128][36];
    __shared__ unsigned Bs[128][36];
    const int tid = threadIdx.x;
    const int wid = tid >> 5, lane = tid & 31;
    const int g = lane >> 2, tg = lane & 3;
    const int wm = (wid >> 2) * 64;      // warp m offset in tile
    const int wn = (wid & 3) * 32;       // warp n offset in tile
    const int m0 = blockIdx.x * 128;
    const int n0 = blockIdx.y * 128;

    float acc[4][4][4];
#pragma unroll
    for (int mt = 0; mt < 4; mt++)
#pragma unroll
        for (int nt = 0; nt < 4; nt++)
#pragma unroll
            for (int c = 0; c < 4; c++) acc[mt][nt][c] = 0.f;

    const int lr = tid >> 3;          // 0..31
    const int lc = (tid & 7) << 2;    // 0,4,...,28
    const float* Ap = A + (size_t)(m0 + lr) * lda + lc;
    const float* Bp = B + (size_t)(n0 + lr) * ldb + lc;

    for (int k0 = 0; k0 < K; k0 += 32) {
        __syncthreads();
#pragma unroll
        for (int r = 0; r < 4; r++) {
            float4 av = *(const float4*)(Ap + (size_t)(r * 32) * lda);
            float4 bv = *(const float4*)(Bp + (size_t)(r * 32) * ldb);
            As[lr + r * 32][lc + 0] = f2tf(av.x);
            As[lr + r * 32][lc + 1] = f2tf(av.y);
            As[lr + r * 32][lc + 2] = f2tf(av.z);
            As[lr + r * 32][lc + 3] = f2tf(av.w);
            Bs[lr + r * 32][lc + 0] = f2tf(bv.x);
            Bs[lr + r * 32][lc + 1] = f2tf(bv.y);
            Bs[lr + r * 32][lc + 2] = f2tf(bv.z);
            Bs[lr + r * 32][lc + 3] = f2tf(bv.w);
        }
        __syncthreads();
        Ap += 32; Bp += 32;
#pragma unroll
        for (int ks = 0; ks < 4; ks++) {
            unsigned af[4][4], bf[4][2];
#pragma unroll
            for (int mt = 0; mt < 4; mt++) {
                int row = wm + mt * 16 + g;
                af[mt][0] = As[row][ks * 8 + tg];
                af[mt][1] = As[row + 8][ks * 8 + tg];
                af[mt][2] = As[row][ks * 8 + tg + 4];
                af[mt][3] = As[row + 8][ks * 8 + tg + 4];
            }
#pragma unroll
            for (int nt = 0; nt < 4; nt++) {
                int col = wn + nt * 8 + g;
                bf[nt][0] = Bs[col][ks * 8 + tg];
                bf[nt][1] = Bs[col][ks * 8 + tg + 4];
            }
#pragma unroll
            for (int mt = 0; mt < 4; mt++)
#pragma unroll
                for (int nt = 0; nt < 4; nt++)
                    mma1688(acc[mt][nt], af[mt], bf[nt]);
        }
    }

#pragma unroll
    for (int mt = 0; mt < 4; mt++) {
#pragma unroll
        for (int nt = 0; nt < 4; nt++) {
            int row = m0 + wm + mt * 16 + g;
            int col = n0 + wn + nt * 8 + 2 * tg;
            float b0 = bias ? bias[col] : 0.f;
            float b1 = bias ? bias[col + 1] : 0.f;
            float v[4];
            v[0] = acc[mt][nt][0] + b0;
            v[1] = acc[mt][nt][1] + b1;
            v[2] = acc[mt][nt][2] + b0;
            v[3] = acc[mt][nt][3] + b1;
#pragma unroll
            for (int c = 0; c < 4; c++) {
                if (ACT == 1) v[c] = 1.f / (1.f + expf(-v[c]));
                if (ACT == 2) v[c] = tanhf(v[c]);
            }
            float* p0 = C + (size_t)row * ldc + col;
            *(float2*)p0 = make_float2(v[0], v[1]);
            *(float2*)(p0 + (size_t)8 * ldc) = make_float2(v[2], v[3]);
        }
    }
}

// ---------------------------------------------------------------------------
// GEMM wrappers
// ---------------------------------------------------------------------------
__global__ void __launch_bounds__(256) gemmP_k(const float* __restrict__ ee) {
    // P[z=b*16+t] = h_b @ W_t^T ; grid (32, 2, 64)
    int z = blockIdx.z;
    int b = z >> 4, t = z & 15;
    gemm_tf32<0>(g_h + (size_t)b * Nn * 256, 256,
                 ee + (size_t)t * 65536, 256,
                 g_P + (size_t)z * Nn * 256, 256, nullptr, 256);
}

__global__ void __launch_bounds__(256) gemm_rz_k() {
    // RZ = sigmoid(AG @ [Wr;Wz]^T + [br;bz]) ; grid (128, 4)
    gemm_tf32<1>(g_AG, 768, g_Wrz, 768, g_RZ, 512, g_brz, 768);
}

__global__ void __launch_bounds__(256) gemm_hh_k(const float* __restrict__ Wh,
                                                 const float* __restrict__ bh) {
    // HH = tanh(AG' @ Wh^T + bh) ; grid (128, 2)
    gemm_tf32<2>(g_AG, 768, Wh, 768, g_HH, 256, bh, 768);
}

// ---------------------------------------------------------------------------
// Setup kernels
// ---------------------------------------------------------------------------
__global__ void prep_Wrz(const float* __restrict__ Wr, const float* __restrict__ Wz,
                         const float* __restrict__ br, const float* __restrict__ bz) {
    int r = blockIdx.x;  // 512
    const float* s = (r < 256) ? (Wr + (size_t)r * 768) : (Wz + (size_t)(r - 256) * 768);
    for (int c = threadIdx.x; c < 768; c += blockDim.x)
        g_Wrz[(size_t)r * 768 + c] = s[c];
    if (threadIdx.x == 0) g_brz[r] = (r < 256) ? br[r] : bz[r - 256];
}

__global__ void init_h(const int* __restrict__ ann_id, const float* __restrict__ te) {
    int n = blockIdx.x;   // b*N+n, 16384
    int i = threadIdx.x;  // 256
    int id = ann_id[n];
    float a = 0.f;
    if (i < 64 && id > 0) a = te[(size_t)(id - 1) * 64 + i];
    if (i < 64) g_ann[(size_t)n * 64 + i] = a;
    g_h[(size_t)n * 256 + i] = (i < 64) ? a : 0.f;
}

// ---------------------------------------------------------------------------
// Per-step kernels
// ---------------------------------------------------------------------------
__global__ void prep_AG() {
    // zero a_in/a_out slots, copy h into slot 2
    int n = blockIdx.x;
    int i = threadIdx.x;
    float* ag = g_AG + (size_t)n * 768;
    ag[i] = 0.f;
    ag[256 + i] = 0.f;
    ag[512 + i] = g_h[(size_t)n * 256 + i];
}

__global__ void __launch_bounds__(128) scatter_k(const int* __restrict__ src,
                                                 const int* __restrict__ dst,
                                                 const int* __restrict__ et,
                                                 const float* __restrict__ eb) {
    // grid B*E = 65536 blocks x 128 threads; dir = tid/64, q = float4 chunk
    int e = blockIdx.x;
    int b = e >> 14;
    int tid = threadIdx.x;
    int dir = tid >> 6, q = tid & 63;
    int s = __ldg(&src[e]);
    int d = __ldg(&dst[e]);
    int t = __ldg(&et[e]);
    const float4* P4 = (const float4*)g_P;
    const float4* eb4 = (const float4*)eb;
    float4 v, bb;
    float* tgt;
    if (dir == 0) {
        // a_out[src] += P[b, t, dst] + eb[t]
        v = P4[(((size_t)(b * 16 + t) * Nn + d) << 6) + q];
        bb = eb4[t * 64 + q];
        tgt = g_AG + (size_t)(b * Nn + s) * 768 + 256 + q * 4;
    } else {
        // a_in[dst] += P[b, t+8, src] + eb[t+8]
        v = P4[(((size_t)(b * 16 + t + 8) * Nn + s) << 6) + q];
        bb = eb4[(t + 8) * 64 + q];
        tgt = g_AG + (size_t)(b * Nn + d) * 768 + q * 4;
    }
    v.x += bb.x; v.y += bb.y; v.z += bb.z; v.w += bb.w;
    asm volatile("red.global.add.v4.f32 [%0], {%1,%2,%3,%4};"
                 :: "l"(tgt), "f"(v.x), "f"(v.y), "f"(v.z), "f"(v.w)
                 : "memory");
}

__global__ void set_rh() {
    int n = blockIdx.x;
    int i = threadIdx.x;
    float r = g_RZ[(size_t)n * 512 + i];
    g_AG[(size_t)n * 768 + 512 + i] = r * g_h[(size_t)n * 256 + i];
}

__global__ void update_h() {
    int n = blockIdx.x;
    int i = threadIdx.x;
    float z = g_RZ[(size_t)n * 512 + 256 + i];
    float h = g_h[(size_t)n * 256 + i];
    float hh = g_HH[(size_t)n * 256 + i];
    g_h[(size_t)n * 256 + i] = (1.f - z) * h + z * hh;
}

// ---------------------------------------------------------------------------
// Readout
// ---------------------------------------------------------------------------
__global__ void readout_k(const float* __restrict__ Wa, const float* __restrict__ ba,
                          const float* __restrict__ Wo, const float* __restrict__ bo) {
    int warp = (blockIdx.x * blockDim.x + threadIdx.x) >> 5;
    int lane = threadIdx.x & 31;
    const float* hrow = g_h + (size_t)warp * 256;
    const float* arow = g_ann + (size_t)warp * 64;
    float sa = 0.f, so = 0.f;
#pragma unroll
    for (int k = lane; k < 320; k += 32) {
        float v = (k < 256) ? hrow[k] : arow[k - 256];
        sa += v * Wa[k];
        so += v * Wo[k];
    }
#pragma unroll
    for (int off = 16; off; off >>= 1) {
        sa += __shfl_xor_sync(0xffffffffu, sa, off);
        so += __shfl_xor_sync(0xffffffffu, so, off);
    }
    if (lane == 0) {
        float atten = 1.f / (1.f + expf(-(sa + ba[0])));
        float ou = tanhf(so + bo[0]);
        g_nodeval[warp] = atten * ou;
    }
}

__global__ void finalize_k(float* __restrict__ out) {
    __shared__ float sh[256];
    int b = blockIdx.x;
    float s = 0.f;
    for (int i = threadIdx.x; i < Nn; i += 256) s += g_nodeval[(size_t)b * Nn + i];
    sh[threadIdx.x] = s;
    __syncthreads();
    for (int k = 128; k; k >>= 1) {
        if (threadIdx.x < k) sh[threadIdx.x] += sh[threadIdx.x + k];
        __syncthreads();
    }
    if (threadIdx.x == 0) out[b] = 1.f / (1.f + expf(-sh[0]));
}

// ---------------------------------------------------------------------------
// Launch
// ---------------------------------------------------------------------------
extern "C" void kernel_launch(void* const* d_in, const int* in_sizes, int n_in,
                              void* d_out, int out_size) {
    (void)in_sizes; (void)n_in; (void)out_size;
    const int* ann_id = (const int*)d_in[0];
    const int* src    = (const int*)d_in[1];
    const int* dst    = (const int*)d_in[2];
    const int* et     = (const int*)d_in[3];
    const float* ee   = (const float*)d_in[4];
    const float* eb   = (const float*)d_in[5];
    const float* te   = (const float*)d_in[6];
    const float* Wr   = (const float*)d_in[7];
    const float* br   = (const float*)d_in[8];
    const float* Wz   = (const float*)d_in[9];
    const float* bz   = (const float*)d_in[10];
    const float* Wh   = (const float*)d_in[11];
    const float* bh   = (const float*)d_in[12];
    const float* Wa   = (const float*)d_in[13];
    const float* ba   = (const float*)d_in[14];
    const float* Wo   = (const float*)d_in[15];
    const float* bo   = (const float*)d_in[16];
    float* out = (float*)d_out;

    prep_Wrz<<<512, 256>>>(Wr, Wz, br, bz);
    init_h<<<Bn * Nn, 256>>>(ann_id, te);

    for (int step = 0; step < 3; step++) {
        prep_AG<<<Bn * Nn, 256>>>();
        gemmP_k<<<dim3(32, 2, 64), 256>>>(ee);
        scatter_k<<<Bn * En, 128>>>(src, dst, et, eb);
        gemm_rz_k<<<dim3(128, 4, 1), 256>>>();
        set_rh<<<Bn * Nn, 256>>>();
        gemm_hh_k<<<dim3(128, 2, 1), 256>>>(Wh, bh);
        update_h<<<Bn * Nn, 256>>>();
    }

    readout_k<<<2048, 256>>>(Wa, ba, Wo, bo);
    finalize_k<<<4, 256>>>(out);
}